// round 2
// baseline (speedup 1.0000x reference)
#include <cuda_runtime.h>
#include <cuda_bf16.h>
#include <cstdint>

// Problem constants (fixed shapes per reference)
#define BDIM 4096   // batch
#define LDIM 4096   // labels
#define HDIM 1024   // hidden

// GEMM tiling
#define BM 128
#define BN 128
#define BK 32
#define STAGES 3
#define LDA 36            // padded floats per smem row (conflict-free fragment LDS)
#define STAGE_FLOATS (BM*LDA + BN*LDA)   // 9216 floats = 36864 B
#define SMEM_BYTES (STAGES * STAGE_FLOATS * 4)  // 110592 B

__device__ float g_diag[LDIM];

// ---------------------------------------------------------------------------
// Kernel 1: diag[j] = sum_k E[j,k]*W[j,k] + b[j]   (fp32 exact, one warp/row)
// ---------------------------------------------------------------------------
__global__ void diag_kernel(const float* __restrict__ E,
                            const float* __restrict__ W,
                            const float* __restrict__ b) {
    int warp = (blockIdx.x * blockDim.x + threadIdx.x) >> 5;
    int lane = threadIdx.x & 31;
    if (warp >= LDIM) return;
    const float4* e4 = reinterpret_cast<const float4*>(E + (size_t)warp * HDIM);
    const float4* w4 = reinterpret_cast<const float4*>(W + (size_t)warp * HDIM);
    float sum = 0.f;
#pragma unroll
    for (int i = 0; i < HDIM / 4 / 32; i++) {   // 8 float4 per lane
        float4 e = e4[lane + i * 32];
        float4 w = w4[lane + i * 32];
        sum += e.x * w.x + e.y * w.y + e.z * w.z + e.w * w.w;
    }
#pragma unroll
    for (int o = 16; o > 0; o >>= 1)
        sum += __shfl_down_sync(0xffffffffu, sum, o);
    if (lane == 0) g_diag[warp] = sum + b[warp];
}

// ---------------------------------------------------------------------------
// TF32 helpers
// ---------------------------------------------------------------------------
__device__ __forceinline__ uint32_t f2tf32(float x) {
    uint32_t r;
    asm volatile("cvt.rna.tf32.f32 %0, %1;\n" : "=r"(r) : "f"(x));
    return r;
}

__device__ __forceinline__ void mma_tf32(float& c0, float& c1, float& c2, float& c3,
                                         uint32_t a0, uint32_t a1, uint32_t a2, uint32_t a3,
                                         uint32_t b0, uint32_t b1) {
    asm volatile(
        "mma.sync.aligned.m16n8k8.row.col.f32.tf32.tf32.f32 "
        "{%0,%1,%2,%3}, {%4,%5,%6,%7}, {%8,%9}, {%0,%1,%2,%3};\n"
        : "+f"(c0), "+f"(c1), "+f"(c2), "+f"(c3)
        : "r"(a0), "r"(a1), "r"(a2), "r"(a3), "r"(b0), "r"(b1));
}

__device__ __forceinline__ void cp_async16(void* smem_ptr, const void* gptr) {
    uint32_t saddr = (uint32_t)__cvta_generic_to_shared(smem_ptr);
    asm volatile("cp.async.cg.shared.global [%0], [%1], 16;\n" :: "r"(saddr), "l"(gptr));
}
__device__ __forceinline__ void cp_commit() {
    asm volatile("cp.async.commit_group;\n" ::: "memory");
}
template <int N>
__device__ __forceinline__ void cp_wait() {
    asm volatile("cp.async.wait_group %0;\n" :: "n"(N) : "memory");
}

// ---------------------------------------------------------------------------
// Kernel 2: C[m,n] = sum_k A[m,k]*W[n,k] + diag[n]   (TF32 mma.sync pipeline)
// ---------------------------------------------------------------------------
__global__ void __launch_bounds__(256, 1)
gemm_tf32_kernel(const float* __restrict__ A,   // [BDIM, HDIM]
                 const float* __restrict__ Bw,  // [LDIM, HDIM]
                 float* __restrict__ C) {       // [BDIM, LDIM]
    extern __shared__ float smem[];

    const int tid = threadIdx.x;
    const int lane = tid & 31;
    const int wid = tid >> 5;
    const int warp_m = wid >> 2;   // 0..1
    const int warp_n = wid & 3;    // 0..3

    const int m0 = blockIdx.y * BM;
    const int n0 = blockIdx.x * BN;

    const float* Ag = A + (size_t)m0 * HDIM;
    const float* Bg = Bw + (size_t)n0 * HDIM;

    // Stage loader: 1024 float4 chunks per tile pair, 256 threads -> 4+4 each
    auto load_stage = [&](int s, int kt) {
        float* as = smem + s * STAGE_FLOATS;
        float* bs = as + BM * LDA;
        const int k0 = kt * BK;
#pragma unroll
        for (int i = 0; i < 4; i++) {
            int c = i * 256 + tid;       // 0..1023
            int row = c >> 3;            // 0..127
            int col = (c & 7) * 4;       // 0..28
            cp_async16(as + row * LDA + col, Ag + (size_t)row * HDIM + k0 + col);
            cp_async16(bs + row * LDA + col, Bg + (size_t)row * HDIM + k0 + col);
        }
        cp_commit();
    };

    float acc[16][4];
#pragma unroll
    for (int i = 0; i < 16; i++)
#pragma unroll
        for (int j = 0; j < 4; j++) acc[i][j] = 0.f;

    constexpr int KT = HDIM / BK;   // 32

    // Prologue: fill STAGES-1 stages
#pragma unroll
    for (int s = 0; s < STAGES - 1; s++) load_stage(s, s);

    for (int kt = 0; kt < KT; kt++) {
        cp_wait<STAGES - 2>();
        __syncthreads();

        // prefetch
        if (kt + STAGES - 1 < KT)
            load_stage((kt + STAGES - 1) % STAGES, kt + STAGES - 1);
        else
            cp_commit();   // keep group count consistent

        const float* as = smem + (kt % STAGES) * STAGE_FLOATS;
        const float* bs = as + BM * LDA;

#pragma unroll
        for (int ks = 0; ks < BK / 8; ks++) {
            const int kc = ks * 8 + (lane & 3);
            uint32_t af[4][4];
#pragma unroll
            for (int mt = 0; mt < 4; mt++) {
                int r = warp_m * 64 + mt * 16 + (lane >> 2);
                af[mt][0] = f2tf32(as[r * LDA + kc]);
                af[mt][1] = f2tf32(as[(r + 8) * LDA + kc]);
                af[mt][2] = f2tf32(as[r * LDA + kc + 4]);
                af[mt][3] = f2tf32(as[(r + 8) * LDA + kc + 4]);
            }
            uint32_t bf[4][2];
#pragma unroll
            for (int nt = 0; nt < 4; nt++) {
                int n = warp_n * 32 + nt * 8 + (lane >> 2);
                bf[nt][0] = f2tf32(bs[n * LDA + kc]);
                bf[nt][1] = f2tf32(bs[n * LDA + kc + 4]);
            }
#pragma unroll
            for (int mt = 0; mt < 4; mt++)
#pragma unroll
                for (int nt = 0; nt < 4; nt++)
                    mma_tf32(acc[mt * 4 + nt][0], acc[mt * 4 + nt][1],
                             acc[mt * 4 + nt][2], acc[mt * 4 + nt][3],
                             af[mt][0], af[mt][1], af[mt][2], af[mt][3],
                             bf[nt][0], bf[nt][1]);
        }
        __syncthreads();
    }

    // Epilogue: + diag[n], float2 stores
#pragma unroll
    for (int mt = 0; mt < 4; mt++) {
#pragma unroll
        for (int nt = 0; nt < 4; nt++) {
            int r = m0 + warp_m * 64 + mt * 16 + (lane >> 2);
            int c = n0 + warp_n * 32 + nt * 8 + 2 * (lane & 3);
            float2 dg = *reinterpret_cast<const float2*>(&g_diag[c]);
            float2 v0 = make_float2(acc[mt * 4 + nt][0] + dg.x,
                                    acc[mt * 4 + nt][1] + dg.y);
            float2 v1 = make_float2(acc[mt * 4 + nt][2] + dg.x,
                                    acc[mt * 4 + nt][3] + dg.y);
            *reinterpret_cast<float2*>(C + (size_t)r * LDIM + c) = v0;
            *reinterpret_cast<float2*>(C + (size_t)(r + 8) * LDIM + c) = v1;
        }
    }
}

// ---------------------------------------------------------------------------
// Launch
// ---------------------------------------------------------------------------
extern "C" void kernel_launch(void* const* d_in, const int* in_sizes, int n_in,
                              void* d_out, int out_size) {
    const float* x = (const float*)d_in[0];   // bert_output [B,H]
    const float* E = (const float*)d_in[1];   // label_embed [L,H]
    const float* W = (const float*)d_in[2];   // W [L,H]
    const float* b = (const float*)d_in[3];   // b [L]
    // d_in[4] = labels, unused by the math
    float* out = (float*)d_out;               // [B,L]

    diag_kernel<<<LDIM / 8, 256>>>(E, W, b);

    cudaFuncSetAttribute(gemm_tf32_kernel,
                         cudaFuncAttributeMaxDynamicSharedMemorySize, SMEM_BYTES);
    dim3 grid(LDIM / BN, BDIM / BM);
    gemm_tf32_kernel<<<grid, 256, SMEM_BYTES>>>(x, W, out);
}

// round 6
// speedup vs baseline: 1.2106x; 1.2106x over previous
#include <cuda_runtime.h>
#include <cuda_bf16.h>
#include <cstdint>

// ---------------------------------------------------------------------------
// Problem constants
// ---------------------------------------------------------------------------
#define BDIM 4096
#define LDIM 4096
#define HDIM 1024

// GEMM tiling
#define BM 128
#define BN 128
#define BK 32
#define KT_CNT (HDIM / BK)        // 32 k-chunks
#define STAGES 3
#define TILE_BYTES (BM * BK * 4)  // 16384 B (unpadded, 128B rows)
#define STAGE_BYTES (2 * TILE_BYTES)          // A + B
#define SMEM_BYTES (STAGES * STAGE_BYTES)     // 98304 B -> 2 CTAs/SM

// ---------------------------------------------------------------------------
// Device scratch: pre-converted tf32 (fp32 bit patterns), k pair-permuted
// within each 8-group: [0,4,1,5,2,6,3,7]
// ---------------------------------------------------------------------------
__device__ float g_diag[LDIM];
__device__ uint32_t g_x32[BDIM * HDIM];
__device__ uint32_t g_w32[LDIM * HDIM];

// ---------------------------------------------------------------------------
// Helpers
// ---------------------------------------------------------------------------
__device__ __forceinline__ uint32_t f2tf32(float x) {
    uint32_t r;
    asm volatile("cvt.rna.tf32.f32 %0, %1;\n" : "=r"(r) : "f"(x));
    return r;
}

__device__ __forceinline__ void mma_tf32(float& c0, float& c1, float& c2, float& c3,
                                         uint32_t a0, uint32_t a1, uint32_t a2, uint32_t a3,
                                         uint32_t b0, uint32_t b1) {
    asm volatile(
        "mma.sync.aligned.m16n8k8.row.col.f32.tf32.tf32.f32 "
        "{%0,%1,%2,%3}, {%4,%5,%6,%7}, {%8,%9}, {%0,%1,%2,%3};\n"
        : "+f"(c0), "+f"(c1), "+f"(c2), "+f"(c3)
        : "r"(a0), "r"(a1), "r"(a2), "r"(a3), "r"(b0), "r"(b1));
}

__device__ __forceinline__ void cp_async16(void* smem_ptr, const void* gptr) {
    uint32_t saddr = (uint32_t)__cvta_generic_to_shared(smem_ptr);
    asm volatile("cp.async.cg.shared.global [%0], [%1], 16;\n" :: "r"(saddr), "l"(gptr));
}
__device__ __forceinline__ void cp_commit() {
    asm volatile("cp.async.commit_group;\n" ::: "memory");
}
template <int N>
__device__ __forceinline__ void cp_wait() {
    asm volatile("cp.async.wait_group %0;\n" :: "n"(N) : "memory");
}

// ---------------------------------------------------------------------------
// Kernel 1a/1b: fp32 -> tf32 bits, with k pair-permutation within 8-groups.
// Each thread handles one 8-float group (two float4 reads, two uint4 writes).
// ---------------------------------------------------------------------------
__device__ __forceinline__ void convert_group(const float* __restrict__ src,
                                              uint32_t* __restrict__ dst, size_t gi) {
    const float4 v0 = reinterpret_cast<const float4*>(src)[2 * gi + 0];  // k 0..3
    const float4 v1 = reinterpret_cast<const float4*>(src)[2 * gi + 1];  // k 4..7
    uint4 o0, o1;
    o0.x = f2tf32(v0.x);  o0.y = f2tf32(v1.x);   // 0,4
    o0.z = f2tf32(v0.y);  o0.w = f2tf32(v1.y);   // 1,5
    o1.x = f2tf32(v0.z);  o1.y = f2tf32(v1.z);   // 2,6
    o1.z = f2tf32(v0.w);  o1.w = f2tf32(v1.w);   // 3,7
    reinterpret_cast<uint4*>(dst)[2 * gi + 0] = o0;
    reinterpret_cast<uint4*>(dst)[2 * gi + 1] = o1;
}

__global__ void convert_x_kernel(const float* __restrict__ src) {
    size_t gi = (size_t)blockIdx.x * blockDim.x + threadIdx.x;  // over N/8
    convert_group(src, g_x32, gi);
}
__global__ void convert_w_kernel(const float* __restrict__ src) {
    size_t gi = (size_t)blockIdx.x * blockDim.x + threadIdx.x;
    convert_group(src, g_w32, gi);
}

// ---------------------------------------------------------------------------
// Kernel 2: diag[j] = sum_k E[j,k]*W[j,k] + b[j]   (fp32 exact)
// ---------------------------------------------------------------------------
__global__ void diag_kernel(const float* __restrict__ E,
                            const float* __restrict__ W,
                            const float* __restrict__ b) {
    int warp = (blockIdx.x * blockDim.x + threadIdx.x) >> 5;
    int lane = threadIdx.x & 31;
    if (warp >= LDIM) return;
    const float4* e4 = reinterpret_cast<const float4*>(E + (size_t)warp * HDIM);
    const float4* w4 = reinterpret_cast<const float4*>(W + (size_t)warp * HDIM);
    float sum = 0.f;
#pragma unroll
    for (int i = 0; i < HDIM / 4 / 32; i++) {
        float4 e = e4[lane + i * 32];
        float4 w = w4[lane + i * 32];
        sum += e.x * w.x + e.y * w.y + e.z * w.z + e.w * w.w;
    }
#pragma unroll
    for (int o = 16; o > 0; o >>= 1)
        sum += __shfl_down_sync(0xffffffffu, sum, o);
    if (lane == 0) g_diag[warp] = sum + b[warp];
}

// ---------------------------------------------------------------------------
// Kernel 3: C[m,n] = sum_k X[m,k]*W[n,k] + diag[n]
// TF32 mma.sync, 3-stage cp.async, unpadded 128B rows with XOR group swizzle:
// smem element (row, group g, pair p) lives at group (g ^ (row & 3)).
// Fragment loads are conflict-free LDS.64.
// ---------------------------------------------------------------------------
__global__ void __launch_bounds__(256, 2)
gemm_tf32_kernel(float* __restrict__ C) {
    extern __shared__ char smem[];

    const int tid = threadIdx.x;
    const int lane = tid & 31;
    const int wid = tid >> 5;
    const int warp_m = wid >> 2;   // 0..1
    const int warp_n = wid & 3;    // 0..3

    const int m0 = blockIdx.y * BM;
    const int n0 = blockIdx.x * BN;

    const uint32_t* Ag = g_x32 + (size_t)m0 * HDIM;
    const uint32_t* Bg = g_w32 + (size_t)n0 * HDIM;

    // Stage loader: per tile 128 rows x 8 chunks(16B). XOR group swizzle on store.
    auto load_stage = [&](int s, int kt) {
        char* as = smem + s * STAGE_BYTES;
        char* bs = as + TILE_BYTES;
        const int k0 = kt * BK;
#pragma unroll
        for (int j = 0; j < 4; j++) {
            int c = j * 256 + tid;        // 0..1023
            int row = c >> 3;             // 0..127
            int ch = c & 7;               // 16B chunk
            int g = ch >> 1, h = ch & 1;
            uint32_t dst = (uint32_t)(row * 128 + (((g ^ (row & 3)) << 1) | h) * 16);
            cp_async16(as + dst, Ag + (size_t)row * HDIM + k0 + ch * 4);
            cp_async16(bs + dst, Bg + (size_t)row * HDIM + k0 + ch * 4);
        }
        cp_commit();
    };

    float acc[16][4];
#pragma unroll
    for (int i = 0; i < 16; i++)
#pragma unroll
        for (int j = 0; j < 4; j++) acc[i][j] = 0.f;

    // Prologue
#pragma unroll
    for (int s = 0; s < STAGES - 1; s++) load_stage(s, s);

    for (int kt = 0; kt < KT_CNT; kt++) {
        cp_wait<STAGES - 2>();
        __syncthreads();

        if (kt + STAGES - 1 < KT_CNT)
            load_stage((kt + STAGES - 1) % STAGES, kt + STAGES - 1);
        else
            cp_commit();   // keep group count consistent

        const char* as = smem + (kt % STAGES) * STAGE_BYTES;
        const char* bs = as + TILE_BYTES;

        const int rA = warp_m * 64 + (lane >> 2);     // base A row
        const int nB = warp_n * 32 + (lane >> 2);     // base B row
        const int t2 = (lane & 3) * 8;                // byte offset of pair

#pragma unroll
        for (int ks = 0; ks < BK / 8; ks++) {
            uint2 afr[4][2];   // [mt][0]=rows r (a0,a2), [1]=row r+8 (a1,a3)
#pragma unroll
            for (int mt = 0; mt < 4; mt++) {
                int r = rA + mt * 16;
                int grp = ks ^ (r & 3);
                uint32_t off = (uint32_t)(r * 128 + grp * 32 + t2);
                afr[mt][0] = *reinterpret_cast<const uint2*>(as + off);
                afr[mt][1] = *reinterpret_cast<const uint2*>(as + off + 8 * 128);
            }
            uint2 bfr[4];
#pragma unroll
            for (int nt = 0; nt < 4; nt++) {
                int n = nB + nt * 8;
                int grp = ks ^ (n & 3);
                uint32_t off = (uint32_t)(n * 128 + grp * 32 + t2);
                bfr[nt] = *reinterpret_cast<const uint2*>(bs + off);
            }
#pragma unroll
            for (int mt = 0; mt < 4; mt++)
#pragma unroll
                for (int nt = 0; nt < 4; nt++)
                    mma_tf32(acc[mt * 4 + nt][0], acc[mt * 4 + nt][1],
                             acc[mt * 4 + nt][2], acc[mt * 4 + nt][3],
                             afr[mt][0].x, afr[mt][1].x, afr[mt][0].y, afr[mt][1].y,
                             bfr[nt].x, bfr[nt].y);
        }
        __syncthreads();
    }

    // Epilogue: + diag[n], float2 stores
#pragma unroll
    for (int mt = 0; mt < 4; mt++) {
#pragma unroll
        for (int nt = 0; nt < 4; nt++) {
            int r = m0 + warp_m * 64 + mt * 16 + (lane >> 2);
            int c = n0 + warp_n * 32 + nt * 8 + 2 * (lane & 3);
            float2 dg = *reinterpret_cast<const float2*>(&g_diag[c]);
            float2 v0 = make_float2(acc[mt * 4 + nt][0] + dg.x,
                                    acc[mt * 4 + nt][1] + dg.y);
            float2 v1 = make_float2(acc[mt * 4 + nt][2] + dg.x,
                                    acc[mt * 4 + nt][3] + dg.y);
            *reinterpret_cast<float2*>(C + (size_t)r * LDIM + c) = v0;
            *reinterpret_cast<float2*>(C + (size_t)(r + 8) * LDIM + c) = v1;
        }
    }
}

// ---------------------------------------------------------------------------
// Launch
// ---------------------------------------------------------------------------
extern "C" void kernel_launch(void* const* d_in, const int* in_sizes, int n_in,
                              void* d_out, int out_size) {
    const float* x = (const float*)d_in[0];   // bert_output [B,H]
    const float* E = (const float*)d_in[1];   // label_embed [L,H]
    const float* W = (const float*)d_in[2];   // W [L,H]
    const float* b = (const float*)d_in[3];   // b [L]
    float* out = (float*)d_out;               // [B,L]

    convert_x_kernel<<<(BDIM * HDIM / 8) / 256, 256>>>(x);
    convert_w_kernel<<<(LDIM * HDIM / 8) / 256, 256>>>(W);
    diag_kernel<<<LDIM / 8, 256>>>(E, W, b);

    cudaFuncSetAttribute(gemm_tf32_kernel,
                         cudaFuncAttributeMaxDynamicSharedMemorySize, SMEM_BYTES);
    dim3 grid(LDIM / BN, BDIM / BM);
    gemm_tf32_kernel<<<grid, 256, SMEM_BYTES>>>(out);
}